// round 14
// baseline (speedup 1.0000x reference)
#include <cuda_runtime.h>
#include <math.h>
#include <stdint.h>

#define NN   40000
#define NE   640000
#define FIN  64
#define FOUT 128
#define NP   12
#define FTOT 768
#define GC   512      /* 4*FOUT */
#define KTOT 192
#define BN   32       /* nodes per fused CTA */

// ---------------- device scratch ----------------
__device__ float d_deg[NN];
__device__ float d_dinv[NN];
__device__ int   d_counts[NN];
__device__ int   d_cursor[NN];
__device__ int   d_offsets[NN + 1];
__device__ int   d_csr[NE];       // source node per CSR slot
__device__ float d_csrw[NE];      // norm weight per CSR slot
__device__ float d_Xt[(size_t)NP * NN * FIN];  // X transposed [t][n][f]
__device__ float d_W1[FIN * GC];               // folded W_x @ W_h_top
__device__ float d_W2[FOUT * GC];              // W_h_bottom
__device__ float d_bias[GC];
__device__ float d_probs[NP];

struct GateW {
    const float* wx[4];
    const float* bx[4];
    const float* wh[4];
    const float* bh[4];
    const float* att;
};

// ---------------- packed f32x2 helpers ----------------
__device__ __forceinline__ unsigned long long pk2(float x) {
    unsigned long long r;
    asm("mov.b64 %0, {%1, %1};" : "=l"(r) : "f"(x));
    return r;
}
__device__ __forceinline__ unsigned long long f2fma(unsigned long long a,
                                                    unsigned long long b,
                                                    unsigned long long c) {
    unsigned long long d;
    asm("fma.rn.f32x2 %0, %1, %2, %3;" : "=l"(d) : "l"(a), "l"(b), "l"(c));
    return d;
}
__device__ __forceinline__ float2 up2(unsigned long long v) {
    float2 r;
    asm("mov.b64 {%0, %1}, %2;" : "=f"(r.x), "=f"(r.y) : "l"(v));
    return r;
}

// ---------------- async copy helpers ----------------
__device__ __forceinline__ uint32_t smem_u32(const void* p) {
    uint32_t a;
    asm("{ .reg .u64 t; cvta.to.shared.u64 t, %1; cvt.u32.u64 %0, t; }" : "=r"(a) : "l"(p));
    return a;
}
__device__ __forceinline__ void cp16(uint32_t dst, const void* src) {
    asm volatile("cp.async.cg.shared.global [%0], [%1], 16;" :: "r"(dst), "l"(src));
}
#define CP_COMMIT() asm volatile("cp.async.commit_group;" ::: "memory")
#define CP_WAIT(n)  asm volatile("cp.async.wait_group %0;" :: "n"(n) : "memory")

// ---------------- small kernels ----------------
__global__ void zero_kernel() {
    int i = blockIdx.x * blockDim.x + threadIdx.x;
    int stride = gridDim.x * blockDim.x;
    for (int idx = i; idx < NN; idx += stride) { d_deg[idx] = 0.f; d_counts[idx] = 0; d_cursor[idx] = 0; }
}

__global__ void deg_kernel(const int* __restrict__ ei, const float* __restrict__ ew) {
    int i = blockIdx.x * blockDim.x + threadIdx.x;
    int stride = gridDim.x * blockDim.x;
    for (int e = i; e < NE; e += stride) {
        int c = ei[NE + e];
        atomicAdd(&d_deg[c], ew[e]);
        atomicAdd(&d_counts[c], 1);
    }
}

__global__ __launch_bounds__(1024) void scan_kernel() {
    int tid = threadIdx.x;
    for (int n = tid; n < NN; n += 1024)
        d_dinv[n] = rsqrtf(d_deg[n] + 1.0f);
    const int CH = 40;
    int base = tid * CH;
    int sum = 0;
#pragma unroll 4
    for (int i = 0; i < CH; i++) { int idx = base + i; if (idx < NN) sum += d_counts[idx]; }
    int lane = tid & 31, wid = tid >> 5;
    int v = sum;
#pragma unroll
    for (int o = 1; o < 32; o <<= 1) { int t = __shfl_up_sync(0xffffffffu, v, o); if (lane >= o) v += t; }
    __shared__ int wsum[32];
    if (lane == 31) wsum[wid] = v;
    __syncthreads();
    if (wid == 0) {
        int w = wsum[lane];
#pragma unroll
        for (int o = 1; o < 32; o <<= 1) { int t = __shfl_up_sync(0xffffffffu, w, o); if (lane >= o) w += t; }
        wsum[lane] = w;
    }
    __syncthreads();
    int excl = v - sum + (wid ? wsum[wid - 1] : 0);
    int run = excl;
#pragma unroll 4
    for (int i = 0; i < CH; i++) {
        int idx = base + i;
        if (idx < NN) { d_offsets[idx] = run; run += d_counts[idx]; }
    }
    if (tid == 1023) d_offsets[NN] = run;
}

__global__ void fill_kernel(const int* __restrict__ ei, const float* __restrict__ ew) {
    int i = blockIdx.x * blockDim.x + threadIdx.x;
    int stride = gridDim.x * blockDim.x;
    for (int e = i; e < NE; e += stride) {
        int c = ei[NE + e];
        int r = ei[e];
        int p = atomicAdd(&d_cursor[c], 1);
        int slot = d_offsets[c] + p;
        d_csr[slot]  = r;
        d_csrw[slot] = d_dinv[r] * ew[e] * d_dinv[c];
    }
}

__global__ __launch_bounds__(512) void prep_kernel(GateW gw) {
    int b = blockIdx.x;
    int c = threadIdx.x;
    int g = c >> 7, j = c & 127;
    if (b < 64) {
        int k = b;
        const float* wx = gw.wx[g];
        const float* wh = gw.wh[g];
        float acc = 0.f;
#pragma unroll 8
        for (int m = 0; m < FOUT; m++) acc += wx[k * FOUT + m] * wh[m * FOUT + j];
        d_W1[k * GC + c] = acc;
    } else if (b < 192) {
        int k = b - 64;
        d_W2[k * GC + c] = gw.wh[g][(FOUT + k) * FOUT + j];
    } else {
        float acc = gw.bh[g][j];
        for (int m = 0; m < FOUT; m++) acc += gw.bx[g][m] * gw.wh[g][m * FOUT + j];
        d_bias[c] = acc;
        if (c == 0) {
            float a[NP], mx = -1e30f, s = 0.f;
            for (int t = 0; t < NP; t++) { a[t] = gw.att[t]; mx = fmaxf(mx, a[t]); }
            for (int t = 0; t < NP; t++) { a[t] = expf(a[t] - mx); s += a[t]; }
            for (int t = 0; t < NP; t++) d_probs[t] = a[t] / s;
        }
    }
}

// X [n][f][t] -> Xt [t][n][f]
__global__ __launch_bounds__(768) void transpose_kernel(const float* __restrict__ X) {
    __shared__ float sv[FTOT];
    int n = blockIdx.x;
    int tid = threadIdx.x;
    sv[tid] = X[(size_t)n * FTOT + tid];
    __syncthreads();
    int t = tid >> 6, f = tid & 63;
    d_Xt[((size_t)t * NN + n) * FIN + f] = sv[f * NP + t];
}

// ---------------- fused 12-step FFMA2 kernel w/ in-kernel gather ----------
// CTA: 32 nodes, 256 threads, loops t=0..11. Weights double-buffered via
// cp.async (B only). S(t) lives in a single SMEM buffer: read during chunks
// 0..3, then overwritten with the gathered S(t+1) (one 4-node group per
// chunk during chunks 4..11) straight from Xt/CSR. No global S at all.
#define SM_B     0                         /* 2 x 32KB B chunk buffers */
#define SM_SS    65536                     /* 32 x 66 floats = 8448    */
#define SM_H     (65536 + 8448)            /* 73984: 32 x 132 floats   */
#define SM_C     (73984 + 16896)           /* 90880: 32 x 132 floats   */
#define SMEM_TOT (90880 + 16896)           /* 107776 */
#define HSTRIDE  132
#define SSTRIDE  66

__device__ __forceinline__ void issue_bchunk(uint32_t sb, int g, int tid) {
    int c = g % 12;
#pragma unroll
    for (int i = 0; i < 8; i++) {
        int op = tid + 256 * i;            // 0..2047
        int row = op >> 7, q = op & 127;
        const float* src = (c < 4) ? &d_W1[(c * 16 + row) * GC + q * 4]
                                   : &d_W2[((c - 4) * 16 + row) * GC + q * 4];
        cp16(sb + SM_B + (g & 1) * 32768 + row * 2048 + q * 16, src);
    }
}

// gather one 4-node group of S(tt) into Ss
__device__ __forceinline__ void gather_group(float* Ss, int tt, int grp,
                                             int node0, int tid) {
    int ndl = grp * 4 + (tid >> 6);
    int f = tid & 63;
    int node = node0 + ndl;
    const float* Xn = d_Xt + (size_t)tt * NN * FIN;
    float dn = d_dinv[node];
    float a1 = dn * dn * Xn[(size_t)node * FIN + f];
    float a2 = 0.f;
    int e = d_offsets[node], end = d_offsets[node + 1];
    for (; e + 1 < end; e += 2) {
        a1 += d_csrw[e]     * Xn[(size_t)d_csr[e] * FIN + f];
        a2 += d_csrw[e + 1] * Xn[(size_t)d_csr[e + 1] * FIN + f];
    }
    if (e < end) a1 += d_csrw[e] * Xn[(size_t)d_csr[e] * FIN + f];
    Ss[ndl * SSTRIDE + f] = a1 + a2;
}

__global__ __launch_bounds__(256, 2) void fused_steps_kernel(float* __restrict__ Hacc_g) {
    extern __shared__ char smem[];
    uint32_t sb = smem_u32(smem);
    int tid = threadIdx.x;
    int tx = tid & 63;        // col pair j = tx*2
    int ty = tid >> 6;        // node group (0..3): nodes ty*8..ty*8+7
    int node0 = blockIdx.x * BN;
    float* Ss = (float*)(smem + SM_SS);
    float* Hs = (float*)(smem + SM_H);
    float* Cs = (float*)(smem + SM_C);

    for (int i = tid; i < BN * HSTRIDE; i += 256) { Hs[i] = 0.f; Cs[i] = 0.f; }

    float2 Ha[8];
#pragma unroll
    for (int i = 0; i < 8; i++) Ha[i] = make_float2(0.f, 0.f);

    float2 bI = *(const float2*)&d_bias[tx * 2];
    float2 bF = *(const float2*)&d_bias[128 + tx * 2];
    float2 bC = *(const float2*)&d_bias[256 + tx * 2];
    float2 bO = *(const float2*)&d_bias[384 + tx * 2];

    // initial S(0) gather + first B chunk
    issue_bchunk(sb, 0, tid);
    CP_COMMIT();
    for (int grp = 0; grp < 8; grp++)
        gather_group(Ss, 0, grp, node0, tid);
    __syncthreads();

    for (int t = 0; t < NP; t++) {
        unsigned long long acc[8][4];
#pragma unroll
        for (int i = 0; i < 8; i++)
#pragma unroll
            for (int j = 0; j < 4; j++) acc[i][j] = 0ull;

        for (int c = 0; c < 12; c++) {
            int g = t * 12 + c;
            if (g < NP * 12 - 1) {
                issue_bchunk(sb, g + 1, tid);
                CP_COMMIT();
                CP_WAIT(1);
            } else {
                CP_WAIT(0);
            }
            __syncthreads();

            const unsigned long long* Bu =
                (const unsigned long long*)(smem + SM_B + (g & 1) * 32768);
            int k0 = (c < 4) ? c * 16 : (c - 4) * 16;
            const float* Arow = (c < 4) ? Ss : Hs;
            int astr = (c < 4) ? SSTRIDE : HSTRIDE;

#pragma unroll
            for (int kg = 0; kg < 8; kg++) {
                float2 av[8];
#pragma unroll
                for (int i = 0; i < 8; i++)
                    av[i] = *(const float2*)&Arow[(ty * 8 + i) * astr + k0 + kg * 2];
#pragma unroll
                for (int k2 = 0; k2 < 2; k2++) {
                    const unsigned long long* Bk = Bu + (kg * 2 + k2) * 256;
                    unsigned long long bb0 = Bk[tx];
                    unsigned long long bb1 = Bk[64 + tx];
                    unsigned long long bb2 = Bk[128 + tx];
                    unsigned long long bb3 = Bk[192 + tx];
#pragma unroll
                    for (int i = 0; i < 8; i++) {
                        unsigned long long aa = pk2(k2 ? av[i].y : av[i].x);
                        acc[i][0] = f2fma(aa, bb0, acc[i][0]);
                        acc[i][1] = f2fma(aa, bb1, acc[i][1]);
                        acc[i][2] = f2fma(aa, bb2, acc[i][2]);
                        acc[i][3] = f2fma(aa, bb3, acc[i][3]);
                    }
                }
            }

            // during H-part chunks, refill Ss with S(t+1), one group per chunk
            if (c >= 4 && t < NP - 1)
                gather_group(Ss, t + 1, c - 4, node0, tid);
            __syncthreads();
        }

        // ---- thread-local LSTM epilogue ----
        float p = d_probs[t];
#pragma unroll
        for (int i = 0; i < 8; i++) {
            int nd = ty * 8 + i;
            float2 zI = up2(acc[i][0]);
            float2 zF = up2(acc[i][1]);
            float2 zC = up2(acc[i][2]);
            float2 zO = up2(acc[i][3]);
            float2 cold = *(const float2*)&Cs[nd * HSTRIDE + tx * 2];
            float I0 = 1.f / (1.f + __expf(-(zI.x + bI.x)));
            float F0 = 1.f / (1.f + __expf(-(zF.x + bF.x)));
            float T0 = 1.f - 2.f / (__expf(2.f * (zC.x + bC.x)) + 1.f);
            float O0 = 1.f / (1.f + __expf(-(zO.x + bO.x)));
            float cn0 = F0 * cold.x + I0 * T0;
            float hh0 = O0 * (1.f - 2.f / (__expf(2.f * cn0) + 1.f));
            float I1 = 1.f / (1.f + __expf(-(zI.y + bI.y)));
            float F1 = 1.f / (1.f + __expf(-(zF.y + bF.y)));
            float T1 = 1.f - 2.f / (__expf(2.f * (zC.y + bC.y)) + 1.f);
            float O1 = 1.f / (1.f + __expf(-(zO.y + bO.y)));
            float cn1 = F1 * cold.y + I1 * T1;
            float hh1 = O1 * (1.f - 2.f / (__expf(2.f * cn1) + 1.f));
            *(float2*)&Cs[nd * HSTRIDE + tx * 2] = make_float2(cn0, cn1);
            *(float2*)&Hs[nd * HSTRIDE + tx * 2] = make_float2(hh0, hh1);
            Ha[i].x += p * hh0;
            Ha[i].y += p * hh1;
        }
        __syncthreads();   // H visible before next step's k>=64 chunks
    }

    // ---- final Hacc writeback ----
#pragma unroll
    for (int i = 0; i < 8; i++) {
        int node = node0 + ty * 8 + i;
        *(float2*)&Hacc_g[node * FOUT + tx * 2] = Ha[i];
    }
}

// ---------------- launch ----------------
extern "C" void kernel_launch(void* const* d_in, const int* in_sizes, int n_in,
                              void* d_out, int out_size) {
    const float* X   = (const float*)d_in[0];
    const int*   ei  = (const int*)d_in[1];
    const float* ew  = (const float*)d_in[2];
    const float* att = (const float*)d_in[3];
    GateW gw;
    for (int g = 0; g < 4; g++) {
        gw.wx[g] = (const float*)d_in[4 + 4 * g];
        gw.bx[g] = (const float*)d_in[5 + 4 * g];
        gw.wh[g] = (const float*)d_in[6 + 4 * g];
        gw.bh[g] = (const float*)d_in[7 + 4 * g];
    }
    gw.att = att;
    float* out = (float*)d_out;

    cudaFuncSetAttribute(fused_steps_kernel, cudaFuncAttributeMaxDynamicSharedMemorySize, SMEM_TOT);

    zero_kernel<<<160, 256>>>();
    deg_kernel<<<640, 256>>>(ei, ew);
    scan_kernel<<<1, 1024>>>();
    fill_kernel<<<640, 256>>>(ei, ew);
    prep_kernel<<<193, 512>>>(gw);
    transpose_kernel<<<NN, 768>>>(X);
    fused_steps_kernel<<<NN / BN, 256, SMEM_TOT>>>(out);
}

// round 15
// speedup vs baseline: 1.2629x; 1.2629x over previous
#include <cuda_runtime.h>
#include <math.h>
#include <stdint.h>

#define NN   40000
#define NE   640000
#define FIN  64
#define FOUT 128
#define NP   12
#define FTOT 768
#define GC   512      /* 4*FOUT */
#define KTOT 192
#define BN   32       /* nodes per fused CTA */

// ---------------- device scratch ----------------
__device__ float d_deg[NN];
__device__ float d_dinv[NN];
__device__ int   d_counts[NN];
__device__ int   d_cursor[NN];
__device__ int   d_offsets[NN + 1];
__device__ int   d_csr[NE];       // source node per CSR slot
__device__ float d_csrw[NE];      // norm weight per CSR slot
__device__ float d_Xt[(size_t)NP * NN * FIN];  // X transposed [t][n][f]
__device__ float d_S[(size_t)NP * NN * FIN];   // [t][n][f]
__device__ float d_W1[FIN * GC];               // folded W_x @ W_h_top
__device__ float d_W2[FOUT * GC];              // W_h_bottom
__device__ float d_bias[GC];
__device__ float d_probs[NP];

struct GateW {
    const float* wx[4];
    const float* bx[4];
    const float* wh[4];
    const float* bh[4];
    const float* att;
};

// ---------------- packed f32x2 helpers ----------------
__device__ __forceinline__ unsigned long long pk2(float x) {
    unsigned long long r;
    asm("mov.b64 %0, {%1, %1};" : "=l"(r) : "f"(x));
    return r;
}
__device__ __forceinline__ unsigned long long f2fma(unsigned long long a,
                                                    unsigned long long b,
                                                    unsigned long long c) {
    unsigned long long d;
    asm("fma.rn.f32x2 %0, %1, %2, %3;" : "=l"(d) : "l"(a), "l"(b), "l"(c));
    return d;
}
__device__ __forceinline__ float2 up2(unsigned long long v) {
    float2 r;
    asm("mov.b64 {%0, %1}, %2;" : "=f"(r.x), "=f"(r.y) : "l"(v));
    return r;
}

// ---------------- async copy helpers ----------------
__device__ __forceinline__ uint32_t smem_u32(const void* p) {
    uint32_t a;
    asm("{ .reg .u64 t; cvta.to.shared.u64 t, %1; cvt.u32.u64 %0, t; }" : "=r"(a) : "l"(p));
    return a;
}
__device__ __forceinline__ void cp16(uint32_t dst, const void* src) {
    asm volatile("cp.async.cg.shared.global [%0], [%1], 16;" :: "r"(dst), "l"(src));
}
#define CP_COMMIT() asm volatile("cp.async.commit_group;" ::: "memory")
#define CP_WAIT(n)  asm volatile("cp.async.wait_group %0;" :: "n"(n) : "memory")

// ---------------- small kernels ----------------
__global__ void zero_kernel() {
    int i = blockIdx.x * blockDim.x + threadIdx.x;
    int stride = gridDim.x * blockDim.x;
    for (int idx = i; idx < NN; idx += stride) { d_deg[idx] = 0.f; d_counts[idx] = 0; d_cursor[idx] = 0; }
}

__global__ void deg_kernel(const int* __restrict__ ei, const float* __restrict__ ew) {
    int i = blockIdx.x * blockDim.x + threadIdx.x;
    int stride = gridDim.x * blockDim.x;
    for (int e = i; e < NE; e += stride) {
        int c = ei[NE + e];
        atomicAdd(&d_deg[c], ew[e]);
        atomicAdd(&d_counts[c], 1);
    }
}

__global__ __launch_bounds__(1024) void scan_kernel() {
    int tid = threadIdx.x;
    for (int n = tid; n < NN; n += 1024)
        d_dinv[n] = rsqrtf(d_deg[n] + 1.0f);
    const int CH = 40;
    int base = tid * CH;
    int sum = 0;
#pragma unroll 4
    for (int i = 0; i < CH; i++) { int idx = base + i; if (idx < NN) sum += d_counts[idx]; }
    int lane = tid & 31, wid = tid >> 5;
    int v = sum;
#pragma unroll
    for (int o = 1; o < 32; o <<= 1) { int t = __shfl_up_sync(0xffffffffu, v, o); if (lane >= o) v += t; }
    __shared__ int wsum[32];
    if (lane == 31) wsum[wid] = v;
    __syncthreads();
    if (wid == 0) {
        int w = wsum[lane];
#pragma unroll
        for (int o = 1; o < 32; o <<= 1) { int t = __shfl_up_sync(0xffffffffu, w, o); if (lane >= o) w += t; }
        wsum[lane] = w;
    }
    __syncthreads();
    int excl = v - sum + (wid ? wsum[wid - 1] : 0);
    int run = excl;
#pragma unroll 4
    for (int i = 0; i < CH; i++) {
        int idx = base + i;
        if (idx < NN) { d_offsets[idx] = run; run += d_counts[idx]; }
    }
    if (tid == 1023) d_offsets[NN] = run;
}

__global__ void fill_kernel(const int* __restrict__ ei, const float* __restrict__ ew) {
    int i = blockIdx.x * blockDim.x + threadIdx.x;
    int stride = gridDim.x * blockDim.x;
    for (int e = i; e < NE; e += stride) {
        int c = ei[NE + e];
        int r = ei[e];
        int p = atomicAdd(&d_cursor[c], 1);
        int slot = d_offsets[c] + p;
        d_csr[slot]  = r;
        d_csrw[slot] = d_dinv[r] * ew[e] * d_dinv[c];
    }
}

__global__ __launch_bounds__(512) void prep_kernel(GateW gw) {
    int b = blockIdx.x;
    int c = threadIdx.x;
    int g = c >> 7, j = c & 127;
    if (b < 64) {
        int k = b;
        const float* wx = gw.wx[g];
        const float* wh = gw.wh[g];
        float acc = 0.f;
#pragma unroll 8
        for (int m = 0; m < FOUT; m++) acc += wx[k * FOUT + m] * wh[m * FOUT + j];
        d_W1[k * GC + c] = acc;
    } else if (b < 192) {
        int k = b - 64;
        d_W2[k * GC + c] = gw.wh[g][(FOUT + k) * FOUT + j];
    } else {
        float acc = gw.bh[g][j];
        for (int m = 0; m < FOUT; m++) acc += gw.bx[g][m] * gw.wh[g][m * FOUT + j];
        d_bias[c] = acc;
        if (c == 0) {
            float a[NP], mx = -1e30f, s = 0.f;
            for (int t = 0; t < NP; t++) { a[t] = gw.att[t]; mx = fmaxf(mx, a[t]); }
            for (int t = 0; t < NP; t++) { a[t] = expf(a[t] - mx); s += a[t]; }
            for (int t = 0; t < NP; t++) d_probs[t] = a[t] / s;
        }
    }
}

// X [n][f][t] -> Xt [t][n][f]
__global__ __launch_bounds__(768) void transpose_kernel(const float* __restrict__ X) {
    __shared__ float sv[FTOT];
    int n = blockIdx.x;
    int tid = threadIdx.x;
    sv[tid] = X[(size_t)n * FTOT + tid];
    __syncthreads();
    int t = tid >> 6, f = tid & 63;
    d_Xt[((size_t)t * NN + n) * FIN + f] = sv[f * NP + t];
}

// all-period gather SpMM: grid (NN/4, NP)
__global__ __launch_bounds__(256) void spmm_all_kernel() {
    int t = blockIdx.y;
    int nd = blockIdx.x * 4 + (threadIdx.x >> 6);
    int f = threadIdx.x & 63;
    const float* Xt = d_Xt + (size_t)t * NN * FIN;
    float dn = d_dinv[nd];
    float acc = dn * dn * Xt[(size_t)nd * FIN + f];
    int beg = d_offsets[nd], end = d_offsets[nd + 1];
    int e = beg;
    float acc2 = 0.f;
    for (; e + 1 < end; e += 2) {
        acc  += d_csrw[e]     * Xt[(size_t)d_csr[e] * FIN + f];
        acc2 += d_csrw[e + 1] * Xt[(size_t)d_csr[e + 1] * FIN + f];
    }
    if (e < end) acc += d_csrw[e] * Xt[(size_t)d_csr[e] * FIN + f];
    __stcs(&d_S[((size_t)t * NN + nd) * FIN + f], acc + acc2);
}

// ---------------- fused 12-step FFMA2 kernel (2 CTAs/SM) ----------------
// CTA: 32 nodes, 256 threads, loops t=0..11 internally.
// Thread cols: {j, 128+j, 256+j, 384+j} for j = (tid&63)*2 (+1) -> epilogue local.
// H, C in SMEM for all steps; Hacc in regs, written once.
#define SM_B     0                       /* 2 x 32KB B chunk buffers */
#define SM_SA    65536                   /* 2 x 2KB S-part A buffers */
#define SM_H     (65536 + 4096)          /* 69632: 32 x 132 floats   */
#define SM_C     (69632 + 16896)         /* 86528: 32 x 132 floats   */
#define SMEM_TOT (86528 + 16896)         /* 103424 */
#define HSTRIDE  132

__device__ __forceinline__ void issue_chunk(uint32_t sb, int g, int node0, int tid) {
    int t = g / 12, c = g % 12;
    if (c < 4 && tid < 128) {
        int row = tid >> 2, q = tid & 3;
        int node = node0 + row;
        const float* src = &d_S[(size_t)t * NN * FIN + (size_t)node * FIN + c * 16 + q * 4];
        cp16(sb + SM_SA + ((t * 4 + c) & 1) * 2048 + row * 64 + q * 16, src);
    }
#pragma unroll
    for (int i = 0; i < 8; i++) {
        int op = tid + 256 * i;            // 0..2047
        int row = op >> 7, q = op & 127;
        const float* src = (c < 4) ? &d_W1[(c * 16 + row) * GC + q * 4]
                                   : &d_W2[((c - 4) * 16 + row) * GC + q * 4];
        cp16(sb + SM_B + (g & 1) * 32768 + row * 2048 + q * 16, src);
    }
}

__global__ __launch_bounds__(256, 2) void fused_steps_kernel(float* __restrict__ Hacc_g) {
    extern __shared__ char smem[];
    uint32_t sb = smem_u32(smem);
    int tid = threadIdx.x;
    int tx = tid & 63;        // col pair j = tx*2
    int ty = tid >> 6;        // node group (0..3): nodes ty*8..ty*8+7
    int node0 = blockIdx.x * BN;
    float* Hs = (float*)(smem + SM_H);
    float* Cs = (float*)(smem + SM_C);

    for (int i = tid; i < BN * HSTRIDE; i += 256) { Hs[i] = 0.f; Cs[i] = 0.f; }

    float2 Ha[8];
#pragma unroll
    for (int i = 0; i < 8; i++) Ha[i] = make_float2(0.f, 0.f);

    float2 bI = *(const float2*)&d_bias[tx * 2];
    float2 bF = *(const float2*)&d_bias[128 + tx * 2];
    float2 bC = *(const float2*)&d_bias[256 + tx * 2];
    float2 bO = *(const float2*)&d_bias[384 + tx * 2];

    __syncthreads();

    issue_chunk(sb, 0, node0, tid);
    CP_COMMIT();

    for (int t = 0; t < NP; t++) {
        unsigned long long acc[8][4];
#pragma unroll
        for (int i = 0; i < 8; i++)
#pragma unroll
            for (int j = 0; j < 4; j++) acc[i][j] = 0ull;

        for (int c = 0; c < 12; c++) {
            int g = t * 12 + c;
            if (g < NP * 12 - 1) {
                issue_chunk(sb, g + 1, node0, tid);
                CP_COMMIT();
                CP_WAIT(1);
            } else {
                CP_WAIT(0);
            }
            __syncthreads();

            const unsigned long long* Bu =
                (const unsigned long long*)(smem + SM_B + (g & 1) * 32768);

            if (c < 4) {
                const float2* Af2 = (const float2*)(smem + SM_SA + ((t * 4 + c) & 1) * 2048);
#pragma unroll
                for (int kg = 0; kg < 8; kg++) {
                    float2 av[8];
#pragma unroll
                    for (int i = 0; i < 8; i++) av[i] = Af2[(ty * 8 + i) * 8 + kg];
#pragma unroll
                    for (int k2 = 0; k2 < 2; k2++) {
                        const unsigned long long* Bk = Bu + (kg * 2 + k2) * 256;
                        unsigned long long bb0 = Bk[tx];
                        unsigned long long bb1 = Bk[64 + tx];
                        unsigned long long bb2 = Bk[128 + tx];
                        unsigned long long bb3 = Bk[192 + tx];
#pragma unroll
                        for (int i = 0; i < 8; i++) {
                            unsigned long long aa = pk2(k2 ? av[i].y : av[i].x);
                            acc[i][0] = f2fma(aa, bb0, acc[i][0]);
                            acc[i][1] = f2fma(aa, bb1, acc[i][1]);
                            acc[i][2] = f2fma(aa, bb2, acc[i][2]);
                            acc[i][3] = f2fma(aa, bb3, acc[i][3]);
                        }
                    }
                }
            } else {
                int k0 = (c - 4) * 16;
#pragma unroll
                for (int kg = 0; kg < 8; kg++) {
                    float2 av[8];
#pragma unroll
                    for (int i = 0; i < 8; i++)
                        av[i] = *(const float2*)&Hs[(ty * 8 + i) * HSTRIDE + k0 + kg * 2];
#pragma unroll
                    for (int k2 = 0; k2 < 2; k2++) {
                        const unsigned long long* Bk = Bu + (kg * 2 + k2) * 256;
                        unsigned long long bb0 = Bk[tx];
                        unsigned long long bb1 = Bk[64 + tx];
                        unsigned long long bb2 = Bk[128 + tx];
                        unsigned long long bb3 = Bk[192 + tx];
#pragma unroll
                        for (int i = 0; i < 8; i++) {
                            unsigned long long aa = pk2(k2 ? av[i].y : av[i].x);
                            acc[i][0] = f2fma(aa, bb0, acc[i][0]);
                            acc[i][1] = f2fma(aa, bb1, acc[i][1]);
                            acc[i][2] = f2fma(aa, bb2, acc[i][2]);
                            acc[i][3] = f2fma(aa, bb3, acc[i][3]);
                        }
                    }
                }
            }
            __syncthreads();
        }

        // ---- thread-local LSTM epilogue ----
        float p = d_probs[t];
#pragma unroll
        for (int i = 0; i < 8; i++) {
            int nd = ty * 8 + i;
            float2 zI = up2(acc[i][0]);
            float2 zF = up2(acc[i][1]);
            float2 zC = up2(acc[i][2]);
            float2 zO = up2(acc[i][3]);
            float2 cold = *(const float2*)&Cs[nd * HSTRIDE + tx * 2];
            float I0 = 1.f / (1.f + __expf(-(zI.x + bI.x)));
            float F0 = 1.f / (1.f + __expf(-(zF.x + bF.x)));
            float T0 = 1.f - 2.f / (__expf(2.f * (zC.x + bC.x)) + 1.f);
            float O0 = 1.f / (1.f + __expf(-(zO.x + bO.x)));
            float cn0 = F0 * cold.x + I0 * T0;
            float hh0 = O0 * (1.f - 2.f / (__expf(2.f * cn0) + 1.f));
            float I1 = 1.f / (1.f + __expf(-(zI.y + bI.y)));
            float F1 = 1.f / (1.f + __expf(-(zF.y + bF.y)));
            float T1 = 1.f - 2.f / (__expf(2.f * (zC.y + bC.y)) + 1.f);
            float O1 = 1.f / (1.f + __expf(-(zO.y + bO.y)));
            float cn1 = F1 * cold.y + I1 * T1;
            float hh1 = O1 * (1.f - 2.f / (__expf(2.f * cn1) + 1.f));
            *(float2*)&Cs[nd * HSTRIDE + tx * 2] = make_float2(cn0, cn1);
            *(float2*)&Hs[nd * HSTRIDE + tx * 2] = make_float2(hh0, hh1);
            Ha[i].x += p * hh0;
            Ha[i].y += p * hh1;
        }
        __syncthreads();   // H visible before next step's k>=64 chunks
    }

    // ---- final Hacc writeback ----
#pragma unroll
    for (int i = 0; i < 8; i++) {
        int node = node0 + ty * 8 + i;
        *(float2*)&Hacc_g[node * FOUT + tx * 2] = Ha[i];
    }
}

// ---------------- launch ----------------
extern "C" void kernel_launch(void* const* d_in, const int* in_sizes, int n_in,
                              void* d_out, int out_size) {
    const float* X   = (const float*)d_in[0];
    const int*   ei  = (const int*)d_in[1];
    const float* ew  = (const float*)d_in[2];
    const float* att = (const float*)d_in[3];
    GateW gw;
    for (int g = 0; g < 4; g++) {
        gw.wx[g] = (const float*)d_in[4 + 4 * g];
        gw.bx[g] = (const float*)d_in[5 + 4 * g];
        gw.wh[g] = (const float*)d_in[6 + 4 * g];
        gw.bh[g] = (const float*)d_in[7 + 4 * g];
    }
    gw.att = att;
    float* out = (float*)d_out;

    // lazy one-time resources (created on the uncaptured correctness call,
    // reused identically during capture)
    static cudaStream_t s2 = 0;
    static cudaEvent_t eFork = 0, eSide = 0;
    if (!s2) {
        cudaStreamCreateWithFlags(&s2, cudaStreamNonBlocking);
        cudaEventCreateWithFlags(&eFork, cudaEventDisableTiming);
        cudaEventCreateWithFlags(&eSide, cudaEventDisableTiming);
        cudaFuncSetAttribute(fused_steps_kernel, cudaFuncAttributeMaxDynamicSharedMemorySize, SMEM_TOT);
    }

    // fork: transpose + prep on side stream; CSR chain on main stream
    cudaEventRecord(eFork, 0);
    cudaStreamWaitEvent(s2, eFork, 0);
    transpose_kernel<<<NN, 768, 0, s2>>>(X);
    prep_kernel<<<193, 512, 0, s2>>>(gw);
    cudaEventRecord(eSide, s2);

    zero_kernel<<<160, 256>>>();
    deg_kernel<<<640, 256>>>(ei, ew);
    scan_kernel<<<1, 1024>>>();
    fill_kernel<<<640, 256>>>(ei, ew);

    // join: spmm needs CSR (main) + Xt (side)
    cudaStreamWaitEvent(0, eSide, 0);
    spmm_all_kernel<<<dim3(NN / 4, NP), 256>>>();
    fused_steps_kernel<<<NN / BN, 256, SMEM_TOT>>>(out);
}

// round 16
// speedup vs baseline: 1.3192x; 1.0446x over previous
#include <cuda_runtime.h>
#include <math.h>
#include <stdint.h>

#define NN   40000
#define NE   640000
#define FIN  64
#define FOUT 128
#define NP   12
#define FTOT 768
#define GC   512      /* 4*FOUT */
#define KTOT 192
#define NFULL 1184    /* full CTAs (32 nodes) = 4 x 296 */
#define NHALF 132     /* half CTAs (16 nodes): 1184*32 + 132*16 = 40000 */

// ---------------- device scratch ----------------
__device__ float d_deg[NN];
__device__ float d_dinv[NN];
__device__ int   d_counts[NN];
__device__ int   d_cursor[NN];
__device__ int   d_offsets[NN + 1];
__device__ int   d_csr[NE];
__device__ float d_csrw[NE];
__device__ float d_Xt[(size_t)NP * NN * FIN];  // X transposed [t][n][f]
__device__ float d_S[(size_t)NP * NN * FIN];   // [t][n][f]
__device__ float d_W1[FIN * GC];
__device__ float d_W2[FOUT * GC];
__device__ float d_bias[GC];
__device__ float d_probs[NP];

struct GateW {
    const float* wx[4];
    const float* bx[4];
    const float* wh[4];
    const float* bh[4];
    const float* att;
};

// ---------------- packed f32x2 helpers ----------------
__device__ __forceinline__ unsigned long long pk2(float x) {
    unsigned long long r;
    asm("mov.b64 %0, {%1, %1};" : "=l"(r) : "f"(x));
    return r;
}
__device__ __forceinline__ unsigned long long f2fma(unsigned long long a,
                                                    unsigned long long b,
                                                    unsigned long long c) {
    unsigned long long d;
    asm("fma.rn.f32x2 %0, %1, %2, %3;" : "=l"(d) : "l"(a), "l"(b), "l"(c));
    return d;
}
__device__ __forceinline__ float2 up2(unsigned long long v) {
    float2 r;
    asm("mov.b64 {%0, %1}, %2;" : "=f"(r.x), "=f"(r.y) : "l"(v));
    return r;
}

// ---------------- async copy helpers ----------------
__device__ __forceinline__ uint32_t smem_u32(const void* p) {
    uint32_t a;
    asm("{ .reg .u64 t; cvta.to.shared.u64 t, %1; cvt.u32.u64 %0, t; }" : "=r"(a) : "l"(p));
    return a;
}
__device__ __forceinline__ void cp16(uint32_t dst, const void* src) {
    asm volatile("cp.async.cg.shared.global [%0], [%1], 16;" :: "r"(dst), "l"(src));
}
#define CP_COMMIT() asm volatile("cp.async.commit_group;" ::: "memory")
#define CP_WAIT(n)  asm volatile("cp.async.wait_group %0;" :: "n"(n) : "memory")

// ---------------- small kernels ----------------
__global__ void zero_kernel() {
    int i = blockIdx.x * blockDim.x + threadIdx.x;
    int stride = gridDim.x * blockDim.x;
    for (int idx = i; idx < NN; idx += stride) { d_deg[idx] = 0.f; d_counts[idx] = 0; d_cursor[idx] = 0; }
}

__global__ void deg_kernel(const int* __restrict__ ei, const float* __restrict__ ew) {
    int i = blockIdx.x * blockDim.x + threadIdx.x;
    int stride = gridDim.x * blockDim.x;
    for (int e = i; e < NE; e += stride) {
        int c = ei[NE + e];
        atomicAdd(&d_deg[c], ew[e]);
        atomicAdd(&d_counts[c], 1);
    }
}

__global__ __launch_bounds__(1024) void scan_kernel() {
    int tid = threadIdx.x;
    for (int n = tid; n < NN; n += 1024)
        d_dinv[n] = rsqrtf(d_deg[n] + 1.0f);
    const int CH = 40;
    int base = tid * CH;
    int sum = 0;
#pragma unroll 4
    for (int i = 0; i < CH; i++) { int idx = base + i; if (idx < NN) sum += d_counts[idx]; }
    int lane = tid & 31, wid = tid >> 5;
    int v = sum;
#pragma unroll
    for (int o = 1; o < 32; o <<= 1) { int t = __shfl_up_sync(0xffffffffu, v, o); if (lane >= o) v += t; }
    __shared__ int wsum[32];
    if (lane == 31) wsum[wid] = v;
    __syncthreads();
    if (wid == 0) {
        int w = wsum[lane];
#pragma unroll
        for (int o = 1; o < 32; o <<= 1) { int t = __shfl_up_sync(0xffffffffu, w, o); if (lane >= o) w += t; }
        wsum[lane] = w;
    }
    __syncthreads();
    int excl = v - sum + (wid ? wsum[wid - 1] : 0);
    int run = excl;
#pragma unroll 4
    for (int i = 0; i < CH; i++) {
        int idx = base + i;
        if (idx < NN) { d_offsets[idx] = run; run += d_counts[idx]; }
    }
    if (tid == 1023) d_offsets[NN] = run;
}

__global__ void fill_kernel(const int* __restrict__ ei, const float* __restrict__ ew) {
    int i = blockIdx.x * blockDim.x + threadIdx.x;
    int stride = gridDim.x * blockDim.x;
    for (int e = i; e < NE; e += stride) {
        int c = ei[NE + e];
        int r = ei[e];
        int p = atomicAdd(&d_cursor[c], 1);
        int slot = d_offsets[c] + p;
        d_csr[slot]  = r;
        d_csrw[slot] = d_dinv[r] * ew[e] * d_dinv[c];
    }
}

__global__ __launch_bounds__(512) void prep_kernel(GateW gw) {
    int b = blockIdx.x;
    int c = threadIdx.x;
    int g = c >> 7, j = c & 127;
    if (b < 64) {
        int k = b;
        const float* wx = gw.wx[g];
        const float* wh = gw.wh[g];
        float acc = 0.f;
#pragma unroll 8
        for (int m = 0; m < FOUT; m++) acc += wx[k * FOUT + m] * wh[m * FOUT + j];
        d_W1[k * GC + c] = acc;
    } else if (b < 192) {
        int k = b - 64;
        d_W2[k * GC + c] = gw.wh[g][(FOUT + k) * FOUT + j];
    } else {
        float acc = gw.bh[g][j];
        for (int m = 0; m < FOUT; m++) acc += gw.bx[g][m] * gw.wh[g][m * FOUT + j];
        d_bias[c] = acc;
        if (c == 0) {
            float a[NP], mx = -1e30f, s = 0.f;
            for (int t = 0; t < NP; t++) { a[t] = gw.att[t]; mx = fmaxf(mx, a[t]); }
            for (int t = 0; t < NP; t++) { a[t] = expf(a[t] - mx); s += a[t]; }
            for (int t = 0; t < NP; t++) d_probs[t] = a[t] / s;
        }
    }
}

// X [n][f][t] -> Xt [t][n][f]
__global__ __launch_bounds__(768) void transpose_kernel(const float* __restrict__ X) {
    __shared__ float sv[FTOT];
    int n = blockIdx.x;
    int tid = threadIdx.x;
    sv[tid] = X[(size_t)n * FTOT + tid];
    __syncthreads();
    int t = tid >> 6, f = tid & 63;
    d_Xt[((size_t)t * NN + n) * FIN + f] = sv[f * NP + t];
}

// all-period gather SpMM: grid (NN/4, NP)
__global__ __launch_bounds__(256) void spmm_all_kernel() {
    int t = blockIdx.y;
    int nd = blockIdx.x * 4 + (threadIdx.x >> 6);
    int f = threadIdx.x & 63;
    const float* Xt = d_Xt + (size_t)t * NN * FIN;
    float dn = d_dinv[nd];
    float acc = dn * dn * Xt[(size_t)nd * FIN + f];
    int beg = d_offsets[nd], end = d_offsets[nd + 1];
    int e = beg;
    float acc2 = 0.f;
    for (; e + 1 < end; e += 2) {
        acc  += d_csrw[e]     * Xt[(size_t)d_csr[e] * FIN + f];
        acc2 += d_csrw[e + 1] * Xt[(size_t)d_csr[e + 1] * FIN + f];
    }
    if (e < end) acc += d_csrw[e] * Xt[(size_t)d_csr[e] * FIN + f];
    __stcs(&d_S[((size_t)t * NN + nd) * FIN + f], acc + acc2);
}

// ---------------- fused 12-step FFMA2 kernel (2 CTAs/SM) ----------------
// Heavy CTA: 32 nodes (NR=8); light tail CTA: 16 nodes (NR=4). 256 threads.
// Single barrier per chunk: CP_WAIT -> barrier -> issue(next) -> compute.
#define SM_B     0                       /* 2 x 32KB B chunk buffers */
#define SM_SA    65536                   /* 2 x 2KB S-part A buffers */
#define SM_H     (65536 + 4096)          /* 69632: 32 x 132 floats   */
#define SM_C     (69632 + 16896)         /* 86528: 32 x 132 floats   */
#define SMEM_TOT (86528 + 16896)         /* 103424 */
#define HSTRIDE  132

__device__ __forceinline__ void issue_chunk(uint32_t sb, int g, int node0, int tid) {
    int t = g / 12, c = g % 12;
    if (c < 4 && tid < 128) {
        int row = tid >> 2, q = tid & 3;
        int node = min(node0 + row, NN - 1);
        const float* src = &d_S[(size_t)t * NN * FIN + (size_t)node * FIN + c * 16 + q * 4];
        cp16(sb + SM_SA + ((t * 4 + c) & 1) * 2048 + row * 64 + q * 16, src);
    }
#pragma unroll
    for (int i = 0; i < 8; i++) {
        int op = tid + 256 * i;            // 0..2047
        int row = op >> 7, q = op & 127;
        const float* src = (c < 4) ? &d_W1[(c * 16 + row) * GC + q * 4]
                                   : &d_W2[((c - 4) * 16 + row) * GC + q * 4];
        cp16(sb + SM_B + (g & 1) * 32768 + row * 2048 + q * 16, src);
    }
}

template<int NR>
__device__ __forceinline__ void fused_body(char* smem, uint32_t sb, int node0,
                                           float* __restrict__ Hacc_g) {
    int tid = threadIdx.x;
    int tx = tid & 63;        // col pair j = tx*2
    int ty = tid >> 6;        // node group: nodes ty*NR .. ty*NR+NR-1
    float* Hs = (float*)(smem + SM_H);
    float* Cs = (float*)(smem + SM_C);

    for (int i = tid; i < 4 * NR * HSTRIDE; i += 256) { Hs[i] = 0.f; Cs[i] = 0.f; }

    float2 Ha[NR];
#pragma unroll
    for (int i = 0; i < NR; i++) Ha[i] = make_float2(0.f, 0.f);

    float2 bI = *(const float2*)&d_bias[tx * 2];
    float2 bF = *(const float2*)&d_bias[128 + tx * 2];
    float2 bC = *(const float2*)&d_bias[256 + tx * 2];
    float2 bO = *(const float2*)&d_bias[384 + tx * 2];

    __syncthreads();
    issue_chunk(sb, 0, node0, tid);
    CP_COMMIT();

    for (int t = 0; t < NP; t++) {
        unsigned long long acc[NR][4];
#pragma unroll
        for (int i = 0; i < NR; i++)
#pragma unroll
            for (int j = 0; j < 4; j++) acc[i][j] = 0ull;

        for (int c = 0; c < 12; c++) {
            int g = t * 12 + c;
            CP_WAIT(0);
            __syncthreads();          // data visible + prev buffer reads done
            if (g < NP * 12 - 1) {
                issue_chunk(sb, g + 1, node0, tid);
                CP_COMMIT();
            }

            const unsigned long long* Bu =
                (const unsigned long long*)(smem + SM_B + (g & 1) * 32768);

            if (c < 4) {
                const float2* Af2 = (const float2*)(smem + SM_SA + ((t * 4 + c) & 1) * 2048);
#pragma unroll
                for (int kg = 0; kg < 8; kg++) {
                    float2 av[NR];
#pragma unroll
                    for (int i = 0; i < NR; i++) av[i] = Af2[(ty * NR + i) * 8 + kg];
#pragma unroll
                    for (int k2 = 0; k2 < 2; k2++) {
                        const unsigned long long* Bk = Bu + (kg * 2 + k2) * 256;
                        unsigned long long bb0 = Bk[tx];
                        unsigned long long bb1 = Bk[64 + tx];
                        unsigned long long bb2 = Bk[128 + tx];
                        unsigned long long bb3 = Bk[192 + tx];
#pragma unroll
                        for (int i = 0; i < NR; i++) {
                            unsigned long long aa = pk2(k2 ? av[i].y : av[i].x);
                            acc[i][0] = f2fma(aa, bb0, acc[i][0]);
                            acc[i][1] = f2fma(aa, bb1, acc[i][1]);
                            acc[i][2] = f2fma(aa, bb2, acc[i][2]);
                            acc[i][3] = f2fma(aa, bb3, acc[i][3]);
                        }
                    }
                }
            } else {
                int k0 = (c - 4) * 16;
#pragma unroll
                for (int kg = 0; kg < 8; kg++) {
                    float2 av[NR];
#pragma unroll
                    for (int i = 0; i < NR; i++)
                        av[i] = *(const float2*)&Hs[(ty * NR + i) * HSTRIDE + k0 + kg * 2];
#pragma unroll
                    for (int k2 = 0; k2 < 2; k2++) {
                        const unsigned long long* Bk = Bu + (kg * 2 + k2) * 256;
                        unsigned long long bb0 = Bk[tx];
                        unsigned long long bb1 = Bk[64 + tx];
                        unsigned long long bb2 = Bk[128 + tx];
                        unsigned long long bb3 = Bk[192 + tx];
#pragma unroll
                        for (int i = 0; i < NR; i++) {
                            unsigned long long aa = pk2(k2 ? av[i].y : av[i].x);
                            acc[i][0] = f2fma(aa, bb0, acc[i][0]);
                            acc[i][1] = f2fma(aa, bb1, acc[i][1]);
                            acc[i][2] = f2fma(aa, bb2, acc[i][2]);
                            acc[i][3] = f2fma(aa, bb3, acc[i][3]);
                        }
                    }
                }
            }
        }

        __syncthreads();   // all warps done reading Hs before epilogue writes

        // ---- thread-local LSTM epilogue ----
        float p = d_probs[t];
#pragma unroll
        for (int i = 0; i < NR; i++) {
            int nd = ty * NR + i;
            float2 zI = up2(acc[i][0]);
            float2 zF = up2(acc[i][1]);
            float2 zC = up2(acc[i][2]);
            float2 zO = up2(acc[i][3]);
            float2 cold = *(const float2*)&Cs[nd * HSTRIDE + tx * 2];
            float I0 = 1.f / (1.f + __expf(-(zI.x + bI.x)));
            float F0 = 1.f / (1.f + __expf(-(zF.x + bF.x)));
            float T0 = 1.f - 2.f / (__expf(2.f * (zC.x + bC.x)) + 1.f);
            float O0 = 1.f / (1.f + __expf(-(zO.x + bO.x)));
            float cn0 = F0 * cold.x + I0 * T0;
            float hh0 = O0 * (1.f - 2.f / (__expf(2.f * cn0) + 1.f));
            float I1 = 1.f / (1.f + __expf(-(zI.y + bI.y)));
            float F1 = 1.f / (1.f + __expf(-(zF.y + bF.y)));
            float T1 = 1.f - 2.f / (__expf(2.f * (zC.y + bC.y)) + 1.f);
            float O1 = 1.f / (1.f + __expf(-(zO.y + bO.y)));
            float cn1 = F1 * cold.y + I1 * T1;
            float hh1 = O1 * (1.f - 2.f / (__expf(2.f * cn1) + 1.f));
            *(float2*)&Cs[nd * HSTRIDE + tx * 2] = make_float2(cn0, cn1);
            *(float2*)&Hs[nd * HSTRIDE + tx * 2] = make_float2(hh0, hh1);
            Ha[i].x += p * hh0;
            Ha[i].y += p * hh1;
        }
        // no post-epilogue barrier needed: next Hs read is >=4 chunk-barriers away
    }

#pragma unroll
    for (int i = 0; i < NR; i++) {
        int node = node0 + ty * NR + i;
        *(float2*)&Hacc_g[node * FOUT + tx * 2] = Ha[i];
    }
}

__global__ __launch_bounds__(256, 2) void fused_steps_kernel(float* __restrict__ Hacc_g) {
    extern __shared__ char smem[];
    uint32_t sb = smem_u32(smem);
    int b = blockIdx.x;
    if (b < NFULL) fused_body<8>(smem, sb, b * 32, Hacc_g);
    else           fused_body<4>(smem, sb, NFULL * 32 + (b - NFULL) * 16, Hacc_g);
}

// ---------------- launch ----------------
extern "C" void kernel_launch(void* const* d_in, const int* in_sizes, int n_in,
                              void* d_out, int out_size) {
    const float* X   = (const float*)d_in[0];
    const int*   ei  = (const int*)d_in[1];
    const float* ew  = (const float*)d_in[2];
    const float* att = (const float*)d_in[3];
    GateW gw;
    for (int g = 0; g < 4; g++) {
        gw.wx[g] = (const float*)d_in[4 + 4 * g];
        gw.bx[g] = (const float*)d_in[5 + 4 * g];
        gw.wh[g] = (const float*)d_in[6 + 4 * g];
        gw.bh[g] = (const float*)d_in[7 + 4 * g];
    }
    gw.att = att;
    float* out = (float*)d_out;

    static cudaStream_t s2 = 0;
    static cudaEvent_t eFork = 0, eSide = 0;
    if (!s2) {
        cudaStreamCreateWithFlags(&s2, cudaStreamNonBlocking);
        cudaEventCreateWithFlags(&eFork, cudaEventDisableTiming);
        cudaEventCreateWithFlags(&eSide, cudaEventDisableTiming);
        cudaFuncSetAttribute(fused_steps_kernel, cudaFuncAttributeMaxDynamicSharedMemorySize, SMEM_TOT);
    }

    // fork: transpose + prep on side stream; CSR chain on main stream
    cudaEventRecord(eFork, 0);
    cudaStreamWaitEvent(s2, eFork, 0);
    transpose_kernel<<<NN, 768, 0, s2>>>(X);
    prep_kernel<<<193, 512, 0, s2>>>(gw);
    cudaEventRecord(eSide, s2);

    zero_kernel<<<160, 256>>>();
    deg_kernel<<<640, 256>>>(ei, ew);
    scan_kernel<<<1, 1024>>>();
    fill_kernel<<<640, 256>>>(ei, ew);

    // join: spmm needs CSR (main) + Xt (side)
    cudaStreamWaitEvent(0, eSide, 0);
    spmm_all_kernel<<<dim3(NN / 4, NP), 256>>>();
    fused_steps_kernel<<<NFULL + NHALF, 256, SMEM_TOT>>>(out);
}